// round 1
// baseline (speedup 1.0000x reference)
#include <cuda_runtime.h>
#include <math_constants.h>

#define BB 8
#define NN 4096
#define NS 1024
#define THREADS 1024

// Per-batch loss scratch (no device allocation allowed).
__device__ float g_batchLoss[BB];

__global__ __launch_bounds__(THREADS, 1)
void emd_batch_kernel(const float* __restrict__ S1,
                      const float* __restrict__ S2,
                      const int*   __restrict__ idxs) {
    __shared__ float4 p1s[NS];     // 16 KB
    __shared__ float4 p2s[NS];     // 16 KB
    __shared__ float  rowmin[NS];  // 4 KB   (squared distance; INF = dead row)
    __shared__ int    rowarg[NS];  // 4 KB   (first argmin col)
    __shared__ float  colDead[NS]; // 4 KB   (0 alive, INF dead -> branchless mask)

    const int b = blockIdx.x;
    const int t = threadIdx.x;

    // ---- gather sampled points into shared ----
    {
        int id = idxs[b * NS + t];
        const float* q1 = S1 + ((long)b * NN + id) * 3;
        const float* q2 = S2 + ((long)b * NN + id) * 3;
        p1s[t] = make_float4(q1[0], q1[1], q1[2], 0.f);
        p2s[t] = make_float4(q2[0], q2[1], q2[2], 0.f);
        colDead[t] = 0.f;
    }
    __syncthreads();

    // ---- init row minima: thread t owns row t, scans all 1024 cols ----
    {
        float4 p = p1s[t];
        float bv = CUDART_INF_F; int bc = 0;
        #pragma unroll 4
        for (int c = 0; c < NS; ++c) {           // uniform c -> LDS broadcast
            float4 q = p2s[c];
            float dx = p.x - q.x, dy = p.y - q.y, dz = p.z - q.z;
            float d2 = fmaf(dz, dz, fmaf(dy, dy, dx * dx));
            if (d2 < bv) { bv = d2; bc = c; }    // ascending c: strict < keeps first col
        }
        rowmin[t] = bv;
        rowarg[t] = bc;
    }
    __syncthreads();

    if (t >= 32) return;   // single warp runs the sequential greedy chain

    const unsigned FULL = 0xffffffffu;
    const int lane = t;
    float loss = 0.f;

    for (int it = 0; it < NS; ++it) {
        // ---- global argmin over row minima (tie-break: lowest row) ----
        float bv = CUDART_INF_F; int br = NS;
        #pragma unroll 8
        for (int j = lane; j < NS; j += 32) {
            float v = rowmin[j];
            if (v < bv) { bv = v; br = j; }      // ascending j: strict < keeps first row
        }
        #pragma unroll
        for (int off = 16; off > 0; off >>= 1) {
            float ov = __shfl_down_sync(FULL, bv, off);
            int   orr = __shfl_down_sync(FULL, br, off);
            if (ov < bv || (ov == bv && orr < br)) { bv = ov; br = orr; }
        }
        int   r  = __shfl_sync(FULL, br, 0);
        float v2 = __shfl_sync(FULL, bv, 0);
        int   c  = rowarg[r];                    // broadcast shared read

        if (lane == 0) {
            loss += sqrtf(v2);                   // accumulate in reference order
            rowmin[r]  = CUDART_INF_F;           // kill row
            colDead[c] = CUDART_INF_F;           // kill col
        }
        __syncwarp(FULL);

        // ---- rows whose cached argmin was c must recompute ----
        for (int base = 0; base < NS; base += 32) {
            int j = base + lane;
            bool aff = (rowarg[j] == c) && (rowmin[j] < CUDART_INF_F);
            unsigned m = __ballot_sync(FULL, aff);
            while (m) {
                int row = base + __ffs(m) - 1;
                m &= m - 1;
                float4 p = p1s[row];             // broadcast
                float rb = CUDART_INF_F; int rc = -1;
                #pragma unroll 8
                for (int cc = lane; cc < NS; cc += 32) {
                    float4 q = p2s[cc];
                    float dx = p.x - q.x, dy = p.y - q.y, dz = p.z - q.z;
                    float d2 = fmaf(dz, dz, fmaf(dy, dy, dx * dx)) + colDead[cc];
                    if (d2 < rb || (d2 == rb && cc < rc && rc >= 0)) { rb = d2; rc = cc; }
                }
                #pragma unroll
                for (int off = 16; off > 0; off >>= 1) {
                    float ov = __shfl_down_sync(FULL, rb, off);
                    int   oc = __shfl_down_sync(FULL, rc, off);
                    if (ov < rb || (ov == rb && (unsigned)oc < (unsigned)rc)) { rb = ov; rc = oc; }
                }
                if (lane == 0) { rowmin[row] = rb; rowarg[row] = rc; }
                __syncwarp(FULL);
            }
        }
        __syncwarp(FULL);
    }

    if (lane == 0) g_batchLoss[b] = loss / (float)NS;
}

__global__ void emd_final_kernel(float* __restrict__ out) {
    float s = 0.f;
    #pragma unroll
    for (int b = 0; b < BB; ++b) s += g_batchLoss[b];
    out[0] = s / (float)BB;
}

extern "C" void kernel_launch(void* const* d_in, const int* in_sizes, int n_in,
                              void* d_out, int out_size) {
    const float* S1  = (const float*)d_in[0];
    const float* S2  = (const float*)d_in[1];
    const int*   idx = (const int*)  d_in[2];
    float* out = (float*)d_out;

    emd_batch_kernel<<<BB, THREADS>>>(S1, S2, idx);
    emd_final_kernel<<<1, 1>>>(out);
}

// round 2
// speedup vs baseline: 2.8442x; 2.8442x over previous
#include <cuda_runtime.h>
#include <math_constants.h>

#define BB 8
#define NN 4096
#define NS 1024
#define THREADS 1024

// Per-batch loss scratch (no device allocation allowed).
__device__ float g_batchLoss[BB];

__global__ __launch_bounds__(THREADS, 1)
void emd_batch_kernel(const float* __restrict__ S1,
                      const float* __restrict__ S2,
                      const int*   __restrict__ idxs) {
    __shared__ float4 p1s[NS];              // 16 KB  S1 points, original row index
    __shared__ float4 p2sC[NS];             // 16 KB  S2 points, COMPACT col position
    __shared__ float  rowminC[NS];          // 4 KB   cached row min (d^2), compact pos
    __shared__ unsigned short rowIdC[NS];   // 2 KB   original row id at compact pos
    __shared__ unsigned short rowargC[NS];  // 2 KB   cached argmin col (ORIGINAL id)
    __shared__ unsigned short rowPos[NS];   // 2 KB   row id -> compact pos
    __shared__ unsigned short colIdC[NS];   // 2 KB   original col id at compact pos
    __shared__ unsigned short colPos[NS];   // 2 KB   col id -> compact pos
    __shared__ unsigned char  colAlive[NS]; // 1 KB

    const int b = blockIdx.x;
    const int t = threadIdx.x;

    // ---- gather sampled points into shared; init compact structures ----
    {
        int id = idxs[b * NS + t];
        const float* q1 = S1 + ((long)b * NN + id) * 3;
        const float* q2 = S2 + ((long)b * NN + id) * 3;
        p1s[t]  = make_float4(q1[0], q1[1], q1[2], 0.f);
        p2sC[t] = make_float4(q2[0], q2[1], q2[2], 0.f);
        rowIdC[t] = (unsigned short)t;
        rowPos[t] = (unsigned short)t;
        colIdC[t] = (unsigned short)t;
        colPos[t] = (unsigned short)t;
        colAlive[t] = 1;
    }
    __syncthreads();

    // ---- init row minima: thread t owns row t (compact pos == row id here) ----
    {
        float4 p = p1s[t];
        float bv = CUDART_INF_F; int bc = 0;
        #pragma unroll 4
        for (int c = 0; c < NS; ++c) {             // uniform c -> LDS broadcast
            float4 q = p2sC[c];
            float dx = p.x - q.x, dy = p.y - q.y, dz = p.z - q.z;
            float d2 = fmaf(dz, dz, fmaf(dy, dy, dx * dx));
            if (d2 < bv) { bv = d2; bc = c; }      // ascending c: strict < keeps first col
        }
        rowminC[t] = bv;
        rowargC[t] = (unsigned short)bc;
    }
    __syncthreads();

    if (t >= 32) return;   // single warp runs the sequential greedy chain

    const unsigned FULL = 0xffffffffu;
    const int lane = t;
    float loss = 0.f;

    for (int it = 0; it < NS; ++it) {
        const int nAlive = NS - it;  // rows == cols alive (uniform, register-resident)
        int   r, csel;
        float v;

        for (;;) {
            // ---- argmin over cached row minima (consecutive shared reads) ----
            float bv = CUDART_INF_F; unsigned br = 0xFFFFFFFFu;
            #pragma unroll 4
            for (int i = lane; i < nAlive; i += 32) {
                float vv = rowminC[i];
                unsigned rid = rowIdC[i];
                if (vv < bv || (vv == bv && rid < br)) { bv = vv; br = rid; }
            }
            unsigned vb = __float_as_uint(bv);          // d2 >= 0: bits order-monotone
            unsigned mn = __reduce_min_sync(FULL, vb);
            r = (int)__reduce_min_sync(FULL, (vb == mn) ? br : 0xFFFFFFFFu);
            v = __uint_as_float(mn);

            csel = rowargC[rowPos[r]];
            if (colAlive[csel]) break;                  // cached entry valid -> true min

            // ---- stale: recompute row r over alive cols (compact, coalesced) ----
            float4 p = p1s[r];
            float rb = CUDART_INF_F; unsigned rc = 0xFFFFFFFFu;
            #pragma unroll 4
            for (int j = lane; j < nAlive; j += 32) {
                float4 q = p2sC[j];
                float dx = p.x - q.x, dy = p.y - q.y, dz = p.z - q.z;
                float d2 = fmaf(dz, dz, fmaf(dy, dy, dx * dx));
                unsigned cid = colIdC[j];
                if (d2 < rb || (d2 == rb && cid < rc)) { rb = d2; rc = cid; }
            }
            unsigned rbb = __float_as_uint(rb);
            unsigned m2  = __reduce_min_sync(FULL, rbb);
            unsigned c2  = __reduce_min_sync(FULL, (rbb == m2) ? rc : 0xFFFFFFFFu);
            if (lane == 0) {
                int pos = rowPos[r];
                rowminC[pos] = __uint_as_float(m2);
                rowargC[pos] = (unsigned short)c2;
            }
            __syncwarp(FULL);
        }

        // ---- accept (r, csel, v): swap-remove row and col ----
        if (lane == 0) {
            loss += sqrtf(v);                           // reference accumulation order

            int pos  = rowPos[r];
            int lastP = nAlive - 1;
            // move last row entry into pos
            rowminC[pos] = rowminC[lastP];
            unsigned short movedR = rowIdC[lastP];
            rowIdC[pos]  = movedR;
            rowargC[pos] = rowargC[lastP];
            rowPos[movedR] = (unsigned short)pos;

            int cpos = colPos[csel];
            // move last col entry into cpos (points physically compacted)
            p2sC[cpos] = p2sC[lastP];
            unsigned short movedC = colIdC[lastP];
            colIdC[cpos] = movedC;
            colPos[movedC] = (unsigned short)cpos;
            colAlive[csel] = 0;
        }
        __syncwarp(FULL);
    }

    if (lane == 0) g_batchLoss[b] = loss / (float)NS;
}

__global__ void emd_final_kernel(float* __restrict__ out) {
    float s = 0.f;
    #pragma unroll
    for (int b = 0; b < BB; ++b) s += g_batchLoss[b];
    out[0] = s / (float)BB;
}

extern "C" void kernel_launch(void* const* d_in, const int* in_sizes, int n_in,
                              void* d_out, int out_size) {
    const float* S1  = (const float*)d_in[0];
    const float* S2  = (const float*)d_in[1];
    const int*   idx = (const int*)  d_in[2];
    float* out = (float*)d_out;

    emd_batch_kernel<<<BB, THREADS>>>(S1, S2, idx);
    emd_final_kernel<<<1, 1>>>(out);
}

// round 3
// speedup vs baseline: 3.8344x; 1.3481x over previous
#include <cuda_runtime.h>
#include <math_constants.h>

#define BB 8
#define NN 4096
#define NS 1024
#define THREADS 1024

// Per-batch loss scratch (no device allocation allowed).
__device__ float g_batchLoss[BB];

// rowKey layout (62 bits used):
//   [61:30] d2 float bits (>=0 -> uint-order == float-order)
//   [29:20] original row id   (tie-break, matches reference row-major argmin)
//   [19:10] compact position  (non-ordering payload)
//   [ 9: 0] cached argmin col (original col id, non-ordering payload)
#define KEY(vb, rid, pos, cs) ((((unsigned long long)(vb)) << 30) | \
                               (((unsigned long long)(rid)) << 20) | \
                               (((unsigned long long)(pos)) << 10) | \
                               ((unsigned long long)(cs)))
#define POS_MASK (1023ULL << 10)

__global__ __launch_bounds__(THREADS, 1)
void emd_batch_kernel(const float* __restrict__ S1,
                      const float* __restrict__ S2,
                      const int*   __restrict__ idxs) {
    __shared__ float4 p1s[NS];                 // 16 KB  S1 points by ORIGINAL row id
    __shared__ float4 p2sC[NS];                // 16 KB  S2 points, COMPACT; .w = col id
    __shared__ unsigned long long rowKey[NS];  //  8 KB  packed key, compact pos
    __shared__ unsigned short colPos[NS];      //  2 KB  col id -> compact pos
    __shared__ unsigned char  colAlive[NS];    //  1 KB

    const int b = blockIdx.x;
    const int t = threadIdx.x;

    // ---- gather sampled points into shared ----
    {
        int id = idxs[b * NS + t];
        const float* q1 = S1 + ((long)b * NN + id) * 3;
        const float* q2 = S2 + ((long)b * NN + id) * 3;
        p1s[t]  = make_float4(q1[0], q1[1], q1[2], 0.f);
        p2sC[t] = make_float4(q2[0], q2[1], q2[2], __int_as_float(t));
        colPos[t] = (unsigned short)t;
        colAlive[t] = 1;
    }
    __syncthreads();

    // ---- init row minima: thread t owns row t (compact pos == ids here) ----
    {
        float4 p = p1s[t];
        float bv = CUDART_INF_F; int bc = 0;
        #pragma unroll 4
        for (int c = 0; c < NS; ++c) {             // uniform c -> LDS broadcast
            float4 q = p2sC[c];
            float dx = p.x - q.x, dy = p.y - q.y, dz = p.z - q.z;
            float d2 = fmaf(dz, dz, fmaf(dy, dy, dx * dx));
            if (d2 < bv) { bv = d2; bc = c; }      // ascending: keeps first (lowest) col
        }
        rowKey[t] = KEY(__float_as_uint(bv), t, t, bc);
    }
    __syncthreads();

    if (t >= 32) return;   // single warp runs the sequential greedy chain

    const unsigned FULL = 0xffffffffu;
    const int lane = t;
    float loss = 0.f;

    for (int it = 0; it < NS; ++it) {
        const int nAlive = NS - it;
        unsigned long long key;
        int rid, pos, csel;
        float v;

        for (;;) {
            // ---- 64-bit lexmin over packed keys (consecutive LDS.64) ----
            unsigned long long bk = ~0ULL;
            #pragma unroll 4
            for (int i = lane; i < nAlive; i += 32) {
                unsigned long long k = rowKey[i];
                if (k < bk) bk = k;
            }
            unsigned hi  = (unsigned)(bk >> 32);
            unsigned lo  = (unsigned)bk;
            unsigned mhi = __reduce_min_sync(FULL, hi);
            unsigned mlo = __reduce_min_sync(FULL, (hi == mhi) ? lo : 0xFFFFFFFFu);
            key  = (((unsigned long long)mhi) << 32) | mlo;
            v    = __uint_as_float((unsigned)(key >> 30));
            rid  = (int)((key >> 20) & 1023u);
            pos  = (int)((key >> 10) & 1023u);
            csel = (int)(key & 1023u);

            if (colAlive[csel]) break;             // cached entry valid -> true min

            // ---- stale: recompute row rid over alive cols (compact, coalesced) ----
            float4 p = p1s[rid];
            float rb = CUDART_INF_F; unsigned rc = 0xFFFFFFFFu;
            #pragma unroll 4
            for (int j = lane; j < nAlive; j += 32) {
                float4 q = p2sC[j];
                float dx = p.x - q.x, dy = p.y - q.y, dz = p.z - q.z;
                float d2 = fmaf(dz, dz, fmaf(dy, dy, dx * dx));
                unsigned cid = (unsigned)__float_as_int(q.w);
                if (d2 < rb || (d2 == rb && cid < rc)) { rb = d2; rc = cid; }
            }
            unsigned rbb = __float_as_uint(rb);
            unsigned m2  = __reduce_min_sync(FULL, rbb);
            unsigned c2  = __reduce_min_sync(FULL, (rbb == m2) ? rc : 0xFFFFFFFFu);
            if (lane == 0)
                rowKey[pos] = KEY(m2, rid, pos, c2);
            __syncwarp(FULL);
        }

        // ---- accept (rid, csel, v): swap-remove row and col ----
        {
            int lastP = nAlive - 1;
            // independent broadcast loads (issue in parallel)
            unsigned long long kLast = rowKey[lastP];
            float4 fLast = p2sC[lastP];
            int cpos = colPos[csel];
            if (lane == 0) {
                loss += sqrtf(v);                  // reference accumulation order
                // move last row key into pos (rewrite its pos field)
                rowKey[pos] = (kLast & ~POS_MASK) | (((unsigned long long)pos) << 10);
                // move last col point into cpos (col id rides in .w)
                p2sC[cpos] = fLast;
                colPos[(unsigned)__float_as_int(fLast.w)] = (unsigned short)cpos;
                colAlive[csel] = 0;
            }
            __syncwarp(FULL);
        }
    }

    if (lane == 0) g_batchLoss[b] = loss / (float)NS;
}

__global__ void emd_final_kernel(float* __restrict__ out) {
    float s = 0.f;
    #pragma unroll
    for (int b = 0; b < BB; ++b) s += g_batchLoss[b];
    out[0] = s / (float)BB;
}

extern "C" void kernel_launch(void* const* d_in, const int* in_sizes, int n_in,
                              void* d_out, int out_size) {
    const float* S1  = (const float*)d_in[0];
    const float* S2  = (const float*)d_in[1];
    const int*   idx = (const int*)  d_in[2];
    float* out = (float*)d_out;

    emd_batch_kernel<<<BB, THREADS>>>(S1, S2, idx);
    emd_final_kernel<<<1, 1>>>(out);
}

// round 5
// speedup vs baseline: 5.5128x; 1.4377x over previous
#include <cuda_runtime.h>
#include <math_constants.h>

#define BB 8
#define NN 4096
#define NS 1024
#define THREADS 1024

// Per-batch loss scratch (no device allocation allowed).
__device__ float g_batchLoss[BB];

// rowKey layout: [63:32] d2 float bits (>=0 -> uint order == float order)
//                [31:16] original row id
//                [15: 0] cached argmin col (original col id)
// Lexicographic u64 order == reference's row-major (value, row, col) argmin order.
// Dead row sentinel = ~0ULL.
#define MKKEY(vb, rid, cs) ((((unsigned long long)(vb)) << 32) | \
                            ((unsigned)(rid) << 16) | (unsigned)(cs))

struct SmemLayout {
    float4 p1s[NS];                 // 16 KB  S1 points by row id
    float4 p2sC[NS];                // 16 KB  S2 points, COMPACT; .w = col id
    unsigned long long rowKey[NS];  //  8 KB  best key, indexed by row id
    unsigned long long rowSec[NS];  //  8 KB  second-best key (~0 = invalid)
    unsigned short colPos[NS];      //  2 KB  col id -> compact pos
    unsigned char  colAlive[NS];    //  1 KB
};
#define SMEM_BYTES ((int)sizeof(SmemLayout))

__global__ __launch_bounds__(THREADS, 1)
void emd_batch_kernel(const float* __restrict__ S1,
                      const float* __restrict__ S2,
                      const int*   __restrict__ idxs) {
    extern __shared__ char smem_raw[];
    SmemLayout* sm = reinterpret_cast<SmemLayout*>(smem_raw);
    float4* p1s  = sm->p1s;
    float4* p2sC = sm->p2sC;
    unsigned long long* rowKey = sm->rowKey;
    unsigned long long* rowSec = sm->rowSec;
    unsigned short* colPos = sm->colPos;
    unsigned char*  colAlive = sm->colAlive;

    const int b = blockIdx.x;
    const int t = threadIdx.x;

    // ---- gather sampled points into shared ----
    {
        int id = idxs[b * NS + t];
        const float* q1 = S1 + ((long)b * NN + id) * 3;
        const float* q2 = S2 + ((long)b * NN + id) * 3;
        p1s[t]  = make_float4(q1[0], q1[1], q1[2], 0.f);
        p2sC[t] = make_float4(q2[0], q2[1], q2[2], __int_as_float(t));
        colPos[t] = (unsigned short)t;
        colAlive[t] = 1;
    }
    __syncthreads();

    // ---- init best-2 per row: thread t owns row t ----
    {
        float4 p = p1s[t];
        float b1 = CUDART_INF_F, b2 = CUDART_INF_F;
        int   c1 = 0, c2 = 0;
        #pragma unroll 4
        for (int c = 0; c < NS; ++c) {             // uniform c -> LDS broadcast
            float4 q = p2sC[c];
            float dx = p.x - q.x, dy = p.y - q.y, dz = p.z - q.z;
            float d2 = fmaf(dz, dz, fmaf(dy, dy, dx * dx));
            if (d2 < b1)      { b2 = b1; c2 = c1; b1 = d2; c1 = c; }
            else if (d2 < b2) { b2 = d2; c2 = c; }   // strict <: keeps lowest col on ties
        }
        rowKey[t] = MKKEY(__float_as_uint(b1), t, c1);
        rowSec[t] = MKKEY(__float_as_uint(b2), t, c2);
    }
    __syncthreads();

    if (t >= 32) return;   // single warp runs the sequential greedy chain

    const unsigned FULL = 0xffffffffu;
    const int lane = t;
    float loss = 0.f;

    // ---- register-resident segment minima: lane owns rows [lane*32, lane*32+32) ----
    unsigned long long mySeg;
    {
        unsigned long long m = ~0ULL;
        #pragma unroll 8
        for (int i = 0; i < 32; ++i) {
            unsigned long long k = rowKey[lane * 32 + i];
            if (k < m) m = k;
        }
        mySeg = m;
    }
    __syncwarp(FULL);

    for (int it = 0; it < NS; ++it) {
        const int nAlive = NS - it;               // alive cols (compact count)
        int rid, csel;
        float v;

        for (;;) {
            // ---- O(1) global lexmin over 32 register segment minima ----
            unsigned hi  = (unsigned)(mySeg >> 32);
            unsigned lo  = (unsigned)mySeg;
            unsigned mhi = __reduce_min_sync(FULL, hi);
            unsigned mlo = __reduce_min_sync(FULL, (hi == mhi) ? lo : 0xFFFFFFFFu);
            v    = __uint_as_float(mhi);
            rid  = (int)(mlo >> 16);
            csel = (int)(mlo & 0xFFFFu);

            if (colAlive[csel]) break;            // cached entry valid -> true min

            const int seg = rid >> 5;
            unsigned long long sec = rowSec[rid];
            bool prom = (sec != ~0ULL) && colAlive[sec & 0xFFFFu];

            if (prom) {
                // ---- promote second-best: no rescan needed ----
                if (lane == 0) { rowKey[rid] = sec; rowSec[rid] = ~0ULL; }
            } else {
                // ---- full rescan of row rid over alive cols; produce best-2 ----
                float4 p = p1s[rid];
                unsigned long long kb1 = ~0ULL, kb2 = ~0ULL;
                #pragma unroll 4
                for (int j = lane; j < nAlive; j += 32) {
                    float4 q = p2sC[j];
                    float dx = p.x - q.x, dy = p.y - q.y, dz = p.z - q.z;
                    float d2 = fmaf(dz, dz, fmaf(dy, dy, dx * dx));
                    unsigned cid = (unsigned)__float_as_int(q.w);
                    unsigned long long kb =
                        (((unsigned long long)__float_as_uint(d2)) << 10) | cid;
                    if (kb < kb1)      { kb2 = kb1; kb1 = kb; }
                    else if (kb < kb2) { kb2 = kb; }
                }
                #pragma unroll
                for (int off = 16; off > 0; off >>= 1) {   // butterfly best-2 merge
                    unsigned long long o1 = __shfl_xor_sync(FULL, kb1, off);
                    unsigned long long o2 = __shfl_xor_sync(FULL, kb2, off);
                    unsigned long long n1 = (o1 < kb1) ? o1 : kb1;
                    unsigned long long mx = (o1 < kb1) ? kb1 : o1;
                    unsigned long long n2 = (o2 < kb2) ? o2 : kb2;
                    kb1 = n1; kb2 = (mx < n2) ? mx : n2;
                }
                if (lane == 0) {
                    rowKey[rid] = MKKEY((unsigned)(kb1 >> 10), rid, (unsigned)(kb1 & 0x3FFu));
                    rowSec[rid] = (kb2 == ~0ULL) ? ~0ULL
                        : MKKEY((unsigned)(kb2 >> 10), rid, (unsigned)(kb2 & 0x3FFu));
                }
            }
            __syncwarp(FULL);

            // ---- recompute this segment's min (32 consecutive LDS.64 + REDUX) ----
            unsigned long long kk = rowKey[seg * 32 + lane];
            unsigned h2 = (unsigned)(kk >> 32), l2 = (unsigned)kk;
            unsigned m2 = __reduce_min_sync(FULL, h2);
            unsigned n2 = __reduce_min_sync(FULL, (h2 == m2) ? l2 : 0xFFFFFFFFu);
            if (lane == seg) mySeg = (((unsigned long long)m2) << 32) | n2;
            __syncwarp(FULL);
        }

        // ---- accept (rid, csel, v): kill row (sentinel) + swap-remove col ----
        {
            const int seg = rid >> 5;
            const int lastP = nAlive - 1;
            float4 fLast = p2sC[lastP];           // independent broadcast loads
            int cpos = colPos[csel];
            if (lane == 0) {
                loss += sqrtf(v);                 // reference accumulation order
                rowKey[rid] = ~0ULL;
                p2sC[cpos] = fLast;               // col id rides in .w
                colPos[(unsigned)__float_as_int(fLast.w)] = (unsigned short)cpos;
                colAlive[csel] = 0;
            }
            __syncwarp(FULL);
            unsigned long long kk = rowKey[seg * 32 + lane];
            unsigned h2 = (unsigned)(kk >> 32), l2 = (unsigned)kk;
            unsigned m2 = __reduce_min_sync(FULL, h2);
            unsigned n2 = __reduce_min_sync(FULL, (h2 == m2) ? l2 : 0xFFFFFFFFu);
            if (lane == seg) mySeg = (((unsigned long long)m2) << 32) | n2;
            __syncwarp(FULL);
        }
    }

    if (lane == 0) g_batchLoss[b] = loss / (float)NS;
}

__global__ void emd_final_kernel(float* __restrict__ out) {
    float s = 0.f;
    #pragma unroll
    for (int b = 0; b < BB; ++b) s += g_batchLoss[b];
    out[0] = s / (float)BB;
}

extern "C" void kernel_launch(void* const* d_in, const int* in_sizes, int n_in,
                              void* d_out, int out_size) {
    const float* S1  = (const float*)d_in[0];
    const float* S2  = (const float*)d_in[1];
    const int*   idx = (const int*)  d_in[2];
    float* out = (float*)d_out;

    // Opt in to >48KB dynamic shared memory (non-stream API: immediate,
    // alloc-free, idempotent — safe under graph capture).
    cudaFuncSetAttribute(emd_batch_kernel,
                         cudaFuncAttributeMaxDynamicSharedMemorySize, SMEM_BYTES);

    emd_batch_kernel<<<BB, THREADS, SMEM_BYTES>>>(S1, S2, idx);
    emd_final_kernel<<<1, 1>>>(out);
}